// round 16
// baseline (speedup 1.0000x reference)
#include <cuda_runtime.h>
#include <cuda_fp16.h>
#include <cstddef>

// Problem constants (fixed by the dataset)
#define NN 50000
#define EE 800000
#define HH 64      // hidden
#define DC 128     // data channels
#define EC 16      // edge channels
#define LL 3
#define EPS_MSG 1e-7f
#define LN_EPS 1e-5f

#define ENCB (EE / 64)            // 12500 enc blocks (exact)
#define NODEB ((NN + 63) / 64)    // 782 node-encoder blocks

// ---------------- device scratch (no cudaMalloc allowed) ----------------
__device__ __half2 g_ea2[(size_t)EE * (HH / 2)];  // encoded edges (ORIGINAL order), fp16
__device__ float g_h[(size_t)NN * HH];            // node state
__device__ float g_z[(size_t)NN * HH];            // pre-normed layer input
__device__ float g_agg[(size_t)NN * HH];          // conv output (agg + root)
__device__ float g_t1[(size_t)NN * 2 * HH];       // MLP hidden
__device__ int   g_deg[NN];
__device__ int   g_rowptr[NN + 1];
__device__ int   g_cursor[NN];
__device__ int2  g_pp[EE];                        // CSR slot -> {src, orig edge}

// ---------------- packed f32x2 FMA helpers ----------------
__device__ __forceinline__ unsigned long long pk2(float x, float y) {
    unsigned long long r;
    asm("mov.b64 %0, {%1,%2};" : "=l"(r) : "f"(x), "f"(y));
    return r;
}
__device__ __forceinline__ float2 upk2(unsigned long long v) {
    float2 r;
    asm("mov.b64 {%0,%1}, %2;" : "=f"(r.x), "=f"(r.y) : "l"(v));
    return r;
}
// c += a * b (a splatted across the pair)
__device__ __forceinline__ float2 ffma2(float a, float2 b, float2 c) {
    unsigned long long ra = pk2(a, a);
    unsigned long long rb = pk2(b.x, b.y);
    unsigned long long rc = pk2(c.x, c.y);
    asm("fma.rn.f32x2 %0, %1, %2, %0;" : "+l"(rc) : "l"(ra), "l"(rb));
    return upk2(rc);
}

// ---------------- mega kernel: edge encode (orig order) + hist + node encoder -
__global__ __launch_bounds__(256) void enc_node_kernel(const float* __restrict__ eattr,
                                                       const int* __restrict__ dst,
                                                       const float* __restrict__ eW,
                                                       const float* __restrict__ eb,
                                                       __half2* __restrict__ ea2,
                                                       int* __restrict__ deg,
                                                       const float* __restrict__ x,
                                                       const float* __restrict__ nW,
                                                       const float* __restrict__ nb,
                                                       float* __restrict__ hout) {
    __shared__ float smem[8192];  // 32 KB, partitioned per branch
    const int tid = threadIdx.x;
    const int warp = tid >> 5, lane = tid & 31;
    const int r0 = warp * 8;

    if (blockIdx.x < ENCB) {
        // ---------------- edge encode branch ----------------
        float* sA = smem;          // 64 x 16
        float* sW = smem + 1024;   // 16 x 64
        const int base = blockIdx.x * 64;

        if (tid < 64) atomicAdd(&deg[dst[base + tid]], 1);  // fused histogram

        *reinterpret_cast<float4*>(&sA[tid * 4]) =
            *reinterpret_cast<const float4*>(&eattr[(size_t)base * EC + tid * 4]);
        *reinterpret_cast<float4*>(&sW[tid * 4]) =
            *reinterpret_cast<const float4*>(&eW[tid * 4]);
        __syncthreads();

        float2 acc[8];
#pragma unroll
        for (int r = 0; r < 8; r++) acc[r] = make_float2(0.f, 0.f);
#pragma unroll
        for (int k4 = 0; k4 < EC; k4 += 4) {
            float4 av[8];
#pragma unroll
            for (int r = 0; r < 8; r++)
                av[r] = *reinterpret_cast<const float4*>(&sA[(r0 + r) * EC + k4]);
            float2 w0 = *reinterpret_cast<const float2*>(&sW[(k4 + 0) * HH + 2 * lane]);
            float2 w1 = *reinterpret_cast<const float2*>(&sW[(k4 + 1) * HH + 2 * lane]);
            float2 w2 = *reinterpret_cast<const float2*>(&sW[(k4 + 2) * HH + 2 * lane]);
            float2 w3 = *reinterpret_cast<const float2*>(&sW[(k4 + 3) * HH + 2 * lane]);
#pragma unroll
            for (int r = 0; r < 8; r++) acc[r] = ffma2(av[r].x, w0, acc[r]);
#pragma unroll
            for (int r = 0; r < 8; r++) acc[r] = ffma2(av[r].y, w1, acc[r]);
#pragma unroll
            for (int r = 0; r < 8; r++) acc[r] = ffma2(av[r].z, w2, acc[r]);
#pragma unroll
            for (int r = 0; r < 8; r++) acc[r] = ffma2(av[r].w, w3, acc[r]);
        }
        const float2 bv = *reinterpret_cast<const float2*>(&eb[2 * lane]);
#pragma unroll
        for (int r = 0; r < 8; r++) {
            float2 ev = make_float2(acc[r].x + bv.x, acc[r].y + bv.y);
            ea2[(size_t)(base + r0 + r) * 32 + lane] = __float22half2_rn(ev);
        }
    } else {
        // ---------------- node encoder branch (K=128 -> 64) ----------------
        constexpr int K = 128, KC = 64;
        float* sA = smem;          // 64 x 64
        float* sW = smem + 4096;   // 64 x 64
        const int m0 = (blockIdx.x - ENCB) * 64;

        float2 acc[8];
#pragma unroll
        for (int r = 0; r < 8; r++) acc[r] = make_float2(0.f, 0.f);

#pragma unroll
        for (int kc = 0; kc < K; kc += KC) {
            if (kc) __syncthreads();
            for (int idx = tid * 4; idx < 64 * KC; idx += 1024) {
                int row = idx / KC, col = idx % KC;
                float4 v = make_float4(0.f, 0.f, 0.f, 0.f);
                if (m0 + row < NN)
                    v = *reinterpret_cast<const float4*>(&x[(size_t)(m0 + row) * K + kc + col]);
                *reinterpret_cast<float4*>(&sA[idx]) = v;
            }
            for (int idx = tid * 4; idx < KC * 64; idx += 1024) {
                int row = idx / 64, col = idx % 64;
                *reinterpret_cast<float4*>(&sW[idx]) =
                    *reinterpret_cast<const float4*>(&nW[(kc + row) * 64 + col]);
            }
            __syncthreads();

#pragma unroll 4
            for (int k4 = 0; k4 < KC; k4 += 4) {
                float4 av[8];
#pragma unroll
                for (int r = 0; r < 8; r++)
                    av[r] = *reinterpret_cast<const float4*>(&sA[(r0 + r) * KC + k4]);
                float2 w0 = *reinterpret_cast<const float2*>(&sW[(k4 + 0) * 64 + 2 * lane]);
                float2 w1 = *reinterpret_cast<const float2*>(&sW[(k4 + 1) * 64 + 2 * lane]);
                float2 w2 = *reinterpret_cast<const float2*>(&sW[(k4 + 2) * 64 + 2 * lane]);
                float2 w3 = *reinterpret_cast<const float2*>(&sW[(k4 + 3) * 64 + 2 * lane]);
#pragma unroll
                for (int r = 0; r < 8; r++) acc[r] = ffma2(av[r].x, w0, acc[r]);
#pragma unroll
                for (int r = 0; r < 8; r++) acc[r] = ffma2(av[r].y, w1, acc[r]);
#pragma unroll
                for (int r = 0; r < 8; r++) acc[r] = ffma2(av[r].z, w2, acc[r]);
#pragma unroll
                for (int r = 0; r < 8; r++) acc[r] = ffma2(av[r].w, w3, acc[r]);
            }
        }
        const float2 bv = *reinterpret_cast<const float2*>(&nb[2 * lane]);
#pragma unroll
        for (int r = 0; r < 8; r++) {
            int row = m0 + r0 + r;
            if (row >= NN) break;  // warp-uniform
            float2 o = make_float2(acc[r].x + bv.x, acc[r].y + bv.y);
            *reinterpret_cast<float2*>(&hout[(size_t)row * 64 + 2 * lane]) = o;
        }
    }
}

// ---------------- CSR scan (single block) -------------------------------------
__global__ void scan_kernel(const int* __restrict__ deg, int* __restrict__ rowptr,
                            int* __restrict__ cursor) {
    __shared__ int sh[1024];
    const int tid = threadIdx.x;
    const int CH = (NN + 1023) / 1024;
    const int base = tid * CH;
    int s = 0;
    for (int i = 0; i < CH; i++) {
        int j = base + i;
        if (j < NN) s += deg[j];
    }
    sh[tid] = s;
    __syncthreads();
    for (int off = 1; off < 1024; off <<= 1) {
        int v = (tid >= off) ? sh[tid - off] : 0;
        __syncthreads();
        sh[tid] += v;
        __syncthreads();
    }
    int run = (tid > 0) ? sh[tid - 1] : 0;
    for (int i = 0; i < CH; i++) {
        int j = base + i;
        if (j < NN) {
            rowptr[j] = run;
            cursor[j] = run;
            run += deg[j];
        }
    }
    if (tid == 0) rowptr[NN] = sh[1023];
}

// thread-per-edge scatter: CSR slot -> packed {src, original edge id}
__global__ void scatter_perm_kernel(const int* __restrict__ src,
                                    const int* __restrict__ dst,
                                    int* __restrict__ cursor,
                                    int2* __restrict__ pp) {
    int e = blockIdx.x * blockDim.x + threadIdx.x;
    if (e < EE) {
        int idx = atomicAdd(&cursor[dst[e]], 1);
        pp[idx] = make_int2(src[e], e);
    }
}

// ---------------- softmax aggregation (depth-3, conditional prefetch) ---------
// One warp per destination node; lane owns features {2l,2l+1}. R14's
// conditional-prefetch shape (measured best issue%) deepened to 3 stages so
// each warp keeps 3 ea2 + 3 z loads in flight over the ~577cyc DRAM latency.
__global__ __launch_bounds__(256, 5) void agg_kernel(const float* __restrict__ z,
                                                     const __half2* __restrict__ ea2,
                                                     const int2* __restrict__ pp,
                                                     const int* __restrict__ rowptr,
                                                     const float* __restrict__ t_ptr,
                                                     float* __restrict__ out) {
    const int w = (blockIdx.x * blockDim.x + threadIdx.x) >> 5;
    if (w >= NN) return;
    const int lane = threadIdx.x & 31;
    const float t2 = *t_ptr * 1.4426950408889634f;  // t * log2(e)

    const int beg = rowptr[w], end = rowptr[w + 1];
    const __half2* ea_l = ea2 + lane;
    const float2* z_l = reinterpret_cast<const float2*>(z) + lane;

    float2 accP = make_float2(0.f, 0.f);
    float2 accM = make_float2(0.f, 0.f);

    // 3-stage pipeline: stages A,B,C in flight; pp prefetched one more ahead
    __half2 eA = __float2half2_rn(0.f), eB = eA, eC = eA;
    float2 zA = make_float2(0.f, 0.f), zB = zA, zC = zA;
    int2 pD = make_int2(0, 0);
    {
        if (beg < end) {
            int2 p = pp[beg];
            eA = __ldcs(ea_l + (size_t)p.y * 32);
            zA = z_l[(size_t)p.x * 32];
        }
        if (beg + 1 < end) {
            int2 p = pp[beg + 1];
            eB = __ldcs(ea_l + (size_t)p.y * 32);
            zB = z_l[(size_t)p.x * 32];
        }
        if (beg + 2 < end) {
            int2 p = pp[beg + 2];
            eC = __ldcs(ea_l + (size_t)p.y * 32);
            zC = z_l[(size_t)p.x * 32];
        }
        if (beg + 3 < end) pD = pp[beg + 3];
    }

    for (int j = beg; j < end; j++) {
        // issue stage j+3 loads; fetch pp for j+4
        __half2 eD = __float2half2_rn(0.f);
        float2 zD = make_float2(0.f, 0.f);
        int2 pE = make_int2(0, 0);
        if (j + 3 < end) {
            eD = __ldcs(ea_l + (size_t)pD.y * 32);
            zD = z_l[(size_t)pD.x * 32];
        }
        if (j + 4 < end) pE = pp[j + 4];

        float2 ev = __half22float2(eA);
        float m0 = fmaxf(zA.x + ev.x, 0.f) + EPS_MSG;
        float m1 = fmaxf(zA.y + ev.y, 0.f) + EPS_MSG;
        // softmax without max-shift: exp args bounded (msg small, t = O(1))
        float p0 = exp2f(m0 * t2);
        float p1 = exp2f(m1 * t2);
        accP.x += p0;
        accP.y += p1;
        accM.x = fmaf(m0, p0, accM.x);
        accM.y = fmaf(m1, p1, accM.y);

        eA = eB; zA = zB;
        eB = eC; zB = zC;
        eC = eD; zC = zD;
        pD = pE;
    }
    const float2 zd = z_l[(size_t)w * 32];
    float2 o;
    o.x = (end > beg ? __fdividef(accM.x, accP.x) : 0.f) + zd.x;
    o.y = (end > beg ? __fdividef(accM.y, accP.y) : 0.f) + zd.y;
    *(reinterpret_cast<float2*>(out) + (size_t)w * 32 + lane) = o;
}

// ---------------- GEMM NOUT=64, K=128, K-chunked smem (32 KB) -----------------
__global__ __launch_bounds__(256, 6) void gemm64_kernel(const float* __restrict__ A,
                                                        const float* __restrict__ W,
                                                        const float* __restrict__ bias,
                                                        const float* __restrict__ resid,
                                                        float* __restrict__ hout,
                                                        const float* __restrict__ png,
                                                        const float* __restrict__ pnb,
                                                        float* __restrict__ zout, int M) {
    constexpr int K = 128, KC = 64;
    __shared__ float sA[64 * KC];  // 16 KB
    __shared__ float sW[KC * 64];  // 16 KB
    const int tid = threadIdx.x;
    const int m0 = blockIdx.x * 64;
    const int warp = tid >> 5, lane = tid & 31;
    const int r0 = warp * 8;

    float2 acc[8];
#pragma unroll
    for (int r = 0; r < 8; r++) acc[r] = make_float2(0.f, 0.f);

#pragma unroll
    for (int kc = 0; kc < K; kc += KC) {
        if (kc) __syncthreads();
        for (int idx = tid * 4; idx < 64 * KC; idx += 1024) {
            int row = idx / KC, col = idx % KC;
            float4 v = make_float4(0.f, 0.f, 0.f, 0.f);
            if (m0 + row < M)
                v = *reinterpret_cast<const float4*>(&A[(size_t)(m0 + row) * K + kc + col]);
            *reinterpret_cast<float4*>(&sA[idx]) = v;
        }
        for (int idx = tid * 4; idx < KC * 64; idx += 1024) {
            int row = idx / 64, col = idx % 64;
            *reinterpret_cast<float4*>(&sW[idx]) =
                *reinterpret_cast<const float4*>(&W[(kc + row) * 64 + col]);
        }
        __syncthreads();

#pragma unroll 4
        for (int k4 = 0; k4 < KC; k4 += 4) {
            float4 av[8];
#pragma unroll
            for (int r = 0; r < 8; r++)
                av[r] = *reinterpret_cast<const float4*>(&sA[(r0 + r) * KC + k4]);
            float2 w0 = *reinterpret_cast<const float2*>(&sW[(k4 + 0) * 64 + 2 * lane]);
            float2 w1 = *reinterpret_cast<const float2*>(&sW[(k4 + 1) * 64 + 2 * lane]);
            float2 w2 = *reinterpret_cast<const float2*>(&sW[(k4 + 2) * 64 + 2 * lane]);
            float2 w3 = *reinterpret_cast<const float2*>(&sW[(k4 + 3) * 64 + 2 * lane]);
#pragma unroll
            for (int r = 0; r < 8; r++) acc[r] = ffma2(av[r].x, w0, acc[r]);
#pragma unroll
            for (int r = 0; r < 8; r++) acc[r] = ffma2(av[r].y, w1, acc[r]);
#pragma unroll
            for (int r = 0; r < 8; r++) acc[r] = ffma2(av[r].z, w2, acc[r]);
#pragma unroll
            for (int r = 0; r < 8; r++) acc[r] = ffma2(av[r].w, w3, acc[r]);
        }
    }

    const float2 bv = *reinterpret_cast<const float2*>(&bias[2 * lane]);
    float2 gv = make_float2(1.f, 1.f), tv = make_float2(0.f, 0.f);
    if (zout) {
        gv = *reinterpret_cast<const float2*>(&png[2 * lane]);
        tv = *reinterpret_cast<const float2*>(&pnb[2 * lane]);
    }
#pragma unroll
    for (int r = 0; r < 8; r++) {
        int row = m0 + r0 + r;
        if (row >= M) break;  // warp-uniform
        float2 o = make_float2(acc[r].x + bv.x, acc[r].y + bv.y);
        if (resid) {
            float2 rv = *reinterpret_cast<const float2*>(&resid[(size_t)row * 64 + 2 * lane]);
            o.x += rv.x;
            o.y += rv.y;
        }
        *reinterpret_cast<float2*>(&hout[(size_t)row * 64 + 2 * lane]) = o;
        if (zout) {
            float s1 = o.x + o.y;
            float s2 = o.x * o.x + o.y * o.y;
#pragma unroll
            for (int off = 16; off; off >>= 1) {
                s1 += __shfl_xor_sync(0xffffffffu, s1, off);
                s2 += __shfl_xor_sync(0xffffffffu, s2, off);
            }
            float mean = s1 * (1.f / 64.f);
            float var = s2 * (1.f / 64.f) - mean * mean;
            float rstd = rsqrtf(var + LN_EPS);
            float z0 = fmaxf((o.x - mean) * rstd * gv.x + tv.x, 0.f);
            float z1 = fmaxf((o.y - mean) * rstd * gv.y + tv.y, 0.f);
            *reinterpret_cast<float2*>(&zout[(size_t)row * 64 + 2 * lane]) =
                make_float2(z0, z1);
        }
    }
}

// ---------------- GEMM NOUT=128, K=64, K-chunked smem (24 KB), fused LN+ReLU --
__global__ __launch_bounds__(256, 4) void gemm128_kernel(const float* __restrict__ A,
                                                         const float* __restrict__ W,
                                                         const float* __restrict__ bias,
                                                         const float* __restrict__ lng,
                                                         const float* __restrict__ lnb,
                                                         float* __restrict__ C, int M) {
    constexpr int K = 64, KC = 32;
    __shared__ float sA[64 * KC];   // 8 KB
    __shared__ float sW[KC * 128];  // 16 KB
    const int tid = threadIdx.x;
    const int m0 = blockIdx.x * 64;
    const int warp = tid >> 5, lane = tid & 31;
    const int r0 = warp * 8;

    float2 acc[8][2];
#pragma unroll
    for (int r = 0; r < 8; r++) {
        acc[r][0] = make_float2(0.f, 0.f);
        acc[r][1] = make_float2(0.f, 0.f);
    }

#pragma unroll
    for (int kc = 0; kc < K; kc += KC) {
        if (kc) __syncthreads();
        for (int idx = tid * 4; idx < 64 * KC; idx += 1024) {
            int row = idx / KC, col = idx % KC;
            float4 v = make_float4(0.f, 0.f, 0.f, 0.f);
            if (m0 + row < M)
                v = *reinterpret_cast<const float4*>(&A[(size_t)(m0 + row) * K + kc + col]);
            *reinterpret_cast<float4*>(&sA[idx]) = v;
        }
        for (int idx = tid * 4; idx < KC * 128; idx += 1024) {
            int row = idx / 128, col = idx % 128;
            *reinterpret_cast<float4*>(&sW[idx]) =
                *reinterpret_cast<const float4*>(&W[(kc + row) * 128 + col]);
        }
        __syncthreads();

#pragma unroll 2
        for (int k4 = 0; k4 < KC; k4 += 4) {
            float4 av[8];
#pragma unroll
            for (int r = 0; r < 8; r++)
                av[r] = *reinterpret_cast<const float4*>(&sA[(r0 + r) * KC + k4]);
            float4 wa = *reinterpret_cast<const float4*>(&sW[(k4 + 0) * 128 + 4 * lane]);
            float4 wb = *reinterpret_cast<const float4*>(&sW[(k4 + 1) * 128 + 4 * lane]);
            float4 wc = *reinterpret_cast<const float4*>(&sW[(k4 + 2) * 128 + 4 * lane]);
            float4 wd = *reinterpret_cast<const float4*>(&sW[(k4 + 3) * 128 + 4 * lane]);
#pragma unroll
            for (int r = 0; r < 8; r++) {
                acc[r][0] = ffma2(av[r].x, make_float2(wa.x, wa.y), acc[r][0]);
                acc[r][1] = ffma2(av[r].x, make_float2(wa.z, wa.w), acc[r][1]);
            }
#pragma unroll
            for (int r = 0; r < 8; r++) {
                acc[r][0] = ffma2(av[r].y, make_float2(wb.x, wb.y), acc[r][0]);
                acc[r][1] = ffma2(av[r].y, make_float2(wb.z, wb.w), acc[r][1]);
            }
#pragma unroll
            for (int r = 0; r < 8; r++) {
                acc[r][0] = ffma2(av[r].z, make_float2(wc.x, wc.y), acc[r][0]);
                acc[r][1] = ffma2(av[r].z, make_float2(wc.z, wc.w), acc[r][1]);
            }
#pragma unroll
            for (int r = 0; r < 8; r++) {
                acc[r][0] = ffma2(av[r].w, make_float2(wd.x, wd.y), acc[r][0]);
                acc[r][1] = ffma2(av[r].w, make_float2(wd.z, wd.w), acc[r][1]);
            }
        }
    }

    const float4 bv = *reinterpret_cast<const float4*>(&bias[4 * lane]);
    const float4 gv = *reinterpret_cast<const float4*>(&lng[4 * lane]);
    const float4 tv = *reinterpret_cast<const float4*>(&lnb[4 * lane]);
#pragma unroll
    for (int r = 0; r < 8; r++) {
        int row = m0 + r0 + r;
        if (row >= M) break;  // warp-uniform
        float v0 = acc[r][0].x + bv.x, v1 = acc[r][0].y + bv.y;
        float v2 = acc[r][1].x + bv.z, v3 = acc[r][1].y + bv.w;
        float s1 = v0 + v1 + v2 + v3;
        float s2 = v0 * v0 + v1 * v1 + v2 * v2 + v3 * v3;
#pragma unroll
        for (int off = 16; off; off >>= 1) {
            s1 += __shfl_xor_sync(0xffffffffu, s1, off);
            s2 += __shfl_xor_sync(0xffffffffu, s2, off);
        }
        float mean = s1 * (1.f / 128.f);
        float var = s2 * (1.f / 128.f) - mean * mean;
        float rstd = rsqrtf(var + LN_EPS);
        v0 = fmaxf((v0 - mean) * rstd * gv.x + tv.x, 0.f);
        v1 = fmaxf((v1 - mean) * rstd * gv.y + tv.y, 0.f);
        v2 = fmaxf((v2 - mean) * rstd * gv.z + tv.z, 0.f);
        v3 = fmaxf((v3 - mean) * rstd * gv.w + tv.w, 0.f);
        *reinterpret_cast<float4*>(&C[(size_t)row * 128 + 4 * lane]) =
            make_float4(v0, v1, v2, v3);
    }
}

// ---------------- launch ------------------------------------------------------
extern "C" void kernel_launch(void* const* d_in, const int* in_sizes, int n_in,
                              void* d_out, int out_size) {
    const float* x      = (const float*)d_in[0];
    const int*   ei     = (const int*)d_in[1];
    const float* eattr  = (const float*)d_in[2];
    const float* node_W = (const float*)d_in[3];
    const float* node_b = (const float*)d_in[4];
    const float* edge_W = (const float*)d_in[5];
    const float* edge_b = (const float*)d_in[6];
    const float* t      = (const float*)d_in[7];
    const float* mlp1_W = (const float*)d_in[8];
    const float* mlp1_b = (const float*)d_in[9];
    const float* ln_g   = (const float*)d_in[10];
    const float* ln_b   = (const float*)d_in[11];
    const float* mlp2_W = (const float*)d_in[12];
    const float* mlp2_b = (const float*)d_in[13];
    const float* blk_g  = (const float*)d_in[14];
    const float* blk_b  = (const float*)d_in[15];
    float* out = (float*)d_out;

    const int* src = ei;
    const int* dst = ei + EE;

    __half2* p_ea2;
    float *p_h, *p_z, *p_agg, *p_t1;
    int *p_deg, *p_rowptr, *p_cursor;
    int2* p_pp;
    cudaGetSymbolAddress((void**)&p_ea2, g_ea2);
    cudaGetSymbolAddress((void**)&p_h, g_h);
    cudaGetSymbolAddress((void**)&p_z, g_z);
    cudaGetSymbolAddress((void**)&p_agg, g_agg);
    cudaGetSymbolAddress((void**)&p_t1, g_t1);
    cudaGetSymbolAddress((void**)&p_deg, g_deg);
    cudaGetSymbolAddress((void**)&p_rowptr, g_rowptr);
    cudaGetSymbolAddress((void**)&p_cursor, g_cursor);
    cudaGetSymbolAddress((void**)&p_pp, g_pp);

    const int warpBlocks = (NN * 32 + 255) / 256;  // 6250 (one warp per node)
    const int gemmBlocks = (NN + 63) / 64;         // 782

    // 1) mega: edge encode (orig order) + histogram + node encoder
    cudaMemsetAsync(p_deg, 0, NN * sizeof(int));
    enc_node_kernel<<<ENCB + NODEB, 256>>>(eattr, dst, edge_W, edge_b, p_ea2,
                                           p_deg, x, node_W, node_b, p_h);
    // 2) scan, 3) scatter (packed pp)
    scan_kernel<<<1, 1024>>>(p_deg, p_rowptr, p_cursor);
    scatter_perm_kernel<<<(EE + 255) / 256, 256>>>(src, dst, p_cursor, p_pp);

    // 4..) layers — agg layer 0 lands in the ncu capture slot
    for (int i = 0; i < LL; i++) {
        const float* zin = (i == 0) ? p_h : p_z;
        agg_kernel<<<warpBlocks, 256>>>(zin, p_ea2, p_pp, p_rowptr, t + i, p_agg);
        gemm128_kernel<<<gemmBlocks, 256>>>(
            p_agg, mlp1_W + (size_t)i * 64 * 128, mlp1_b + i * 128,
            ln_g + i * 128, ln_b + i * 128, p_t1, NN);
        const bool last = (i == LL - 1);
        const float* png = last ? blk_g : blk_g + (i + 1) * HH;  // final norm uses blk[0]
        const float* pnb = last ? blk_b : blk_b + (i + 1) * HH;
        float* zo = last ? out : p_z;
        gemm64_kernel<<<gemmBlocks, 256>>>(
            p_t1, mlp2_W + (size_t)i * 128 * 64, mlp2_b + i * 64,
            (i > 0 ? p_h : nullptr), p_h, png, pnb, zo, NN);
    }
}

// round 17
// speedup vs baseline: 1.0448x; 1.0448x over previous
#include <cuda_runtime.h>
#include <cuda_fp16.h>
#include <cstddef>

// Problem constants (fixed by the dataset)
#define NN 50000
#define EE 800000
#define HH 64      // hidden
#define DC 128     // data channels
#define EC 16      // edge channels
#define LL 3
#define EPS_MSG 1e-7f
#define LN_EPS 1e-5f

#define ENCB (EE / 64)            // 12500 enc blocks (exact)
#define NODEB ((NN + 63) / 64)    // 782 node-encoder blocks

// ---------------- device scratch (no cudaMalloc allowed) ----------------
__device__ __half2 g_ea2[(size_t)EE * (HH / 2)];  // encoded edges (ORIGINAL order), fp16
__device__ float g_h[(size_t)NN * HH];            // node state
__device__ float g_z[(size_t)NN * HH];            // pre-normed layer input
__device__ float g_agg[(size_t)NN * HH];          // conv output (agg + root)
__device__ float g_t1[(size_t)NN * 2 * HH];       // MLP hidden
__device__ int   g_deg[NN];
__device__ int   g_rowptr[NN + 1];
__device__ int   g_cursor[NN];
__device__ int2  g_pp[EE];                        // CSR slot -> {src, orig edge}

// ---------------- packed f32x2 FMA helpers ----------------
__device__ __forceinline__ unsigned long long pk2(float x, float y) {
    unsigned long long r;
    asm("mov.b64 %0, {%1,%2};" : "=l"(r) : "f"(x), "f"(y));
    return r;
}
__device__ __forceinline__ float2 upk2(unsigned long long v) {
    float2 r;
    asm("mov.b64 {%0,%1}, %2;" : "=f"(r.x), "=f"(r.y) : "l"(v));
    return r;
}
// c += a * b (a splatted across the pair)
__device__ __forceinline__ float2 ffma2(float a, float2 b, float2 c) {
    unsigned long long ra = pk2(a, a);
    unsigned long long rb = pk2(b.x, b.y);
    unsigned long long rc = pk2(c.x, c.y);
    asm("fma.rn.f32x2 %0, %1, %2, %0;" : "+l"(rc) : "l"(ra), "l"(rb));
    return upk2(rc);
}

// ---------------- mega kernel: edge encode (orig order) + hist + node encoder -
__global__ __launch_bounds__(256) void enc_node_kernel(const float* __restrict__ eattr,
                                                       const int* __restrict__ dst,
                                                       const float* __restrict__ eW,
                                                       const float* __restrict__ eb,
                                                       __half2* __restrict__ ea2,
                                                       int* __restrict__ deg,
                                                       const float* __restrict__ x,
                                                       const float* __restrict__ nW,
                                                       const float* __restrict__ nb,
                                                       float* __restrict__ hout) {
    __shared__ float smem[8192];  // 32 KB, partitioned per branch
    const int tid = threadIdx.x;
    const int warp = tid >> 5, lane = tid & 31;
    const int r0 = warp * 8;

    if (blockIdx.x < ENCB) {
        // ---------------- edge encode branch ----------------
        float* sA = smem;          // 64 x 16
        float* sW = smem + 1024;   // 16 x 64
        const int base = blockIdx.x * 64;

        if (tid < 64) atomicAdd(&deg[dst[base + tid]], 1);  // fused histogram

        *reinterpret_cast<float4*>(&sA[tid * 4]) =
            *reinterpret_cast<const float4*>(&eattr[(size_t)base * EC + tid * 4]);
        *reinterpret_cast<float4*>(&sW[tid * 4]) =
            *reinterpret_cast<const float4*>(&eW[tid * 4]);
        __syncthreads();

        float2 acc[8];
#pragma unroll
        for (int r = 0; r < 8; r++) acc[r] = make_float2(0.f, 0.f);
#pragma unroll
        for (int k4 = 0; k4 < EC; k4 += 4) {
            float4 av[8];
#pragma unroll
            for (int r = 0; r < 8; r++)
                av[r] = *reinterpret_cast<const float4*>(&sA[(r0 + r) * EC + k4]);
            float2 w0 = *reinterpret_cast<const float2*>(&sW[(k4 + 0) * HH + 2 * lane]);
            float2 w1 = *reinterpret_cast<const float2*>(&sW[(k4 + 1) * HH + 2 * lane]);
            float2 w2 = *reinterpret_cast<const float2*>(&sW[(k4 + 2) * HH + 2 * lane]);
            float2 w3 = *reinterpret_cast<const float2*>(&sW[(k4 + 3) * HH + 2 * lane]);
#pragma unroll
            for (int r = 0; r < 8; r++) acc[r] = ffma2(av[r].x, w0, acc[r]);
#pragma unroll
            for (int r = 0; r < 8; r++) acc[r] = ffma2(av[r].y, w1, acc[r]);
#pragma unroll
            for (int r = 0; r < 8; r++) acc[r] = ffma2(av[r].z, w2, acc[r]);
#pragma unroll
            for (int r = 0; r < 8; r++) acc[r] = ffma2(av[r].w, w3, acc[r]);
        }
        const float2 bv = *reinterpret_cast<const float2*>(&eb[2 * lane]);
#pragma unroll
        for (int r = 0; r < 8; r++) {
            float2 ev = make_float2(acc[r].x + bv.x, acc[r].y + bv.y);
            ea2[(size_t)(base + r0 + r) * 32 + lane] = __float22half2_rn(ev);
        }
    } else {
        // ---------------- node encoder branch (K=128 -> 64) ----------------
        constexpr int K = 128, KC = 64;
        float* sA = smem;          // 64 x 64
        float* sW = smem + 4096;   // 64 x 64
        const int m0 = (blockIdx.x - ENCB) * 64;

        float2 acc[8];
#pragma unroll
        for (int r = 0; r < 8; r++) acc[r] = make_float2(0.f, 0.f);

#pragma unroll
        for (int kc = 0; kc < K; kc += KC) {
            if (kc) __syncthreads();
            for (int idx = tid * 4; idx < 64 * KC; idx += 1024) {
                int row = idx / KC, col = idx % KC;
                float4 v = make_float4(0.f, 0.f, 0.f, 0.f);
                if (m0 + row < NN)
                    v = *reinterpret_cast<const float4*>(&x[(size_t)(m0 + row) * K + kc + col]);
                *reinterpret_cast<float4*>(&sA[idx]) = v;
            }
            for (int idx = tid * 4; idx < KC * 64; idx += 1024) {
                int row = idx / 64, col = idx % 64;
                *reinterpret_cast<float4*>(&sW[idx]) =
                    *reinterpret_cast<const float4*>(&nW[(kc + row) * 64 + col]);
            }
            __syncthreads();

#pragma unroll 4
            for (int k4 = 0; k4 < KC; k4 += 4) {
                float4 av[8];
#pragma unroll
                for (int r = 0; r < 8; r++)
                    av[r] = *reinterpret_cast<const float4*>(&sA[(r0 + r) * KC + k4]);
                float2 w0 = *reinterpret_cast<const float2*>(&sW[(k4 + 0) * 64 + 2 * lane]);
                float2 w1 = *reinterpret_cast<const float2*>(&sW[(k4 + 1) * 64 + 2 * lane]);
                float2 w2 = *reinterpret_cast<const float2*>(&sW[(k4 + 2) * 64 + 2 * lane]);
                float2 w3 = *reinterpret_cast<const float2*>(&sW[(k4 + 3) * 64 + 2 * lane]);
#pragma unroll
                for (int r = 0; r < 8; r++) acc[r] = ffma2(av[r].x, w0, acc[r]);
#pragma unroll
                for (int r = 0; r < 8; r++) acc[r] = ffma2(av[r].y, w1, acc[r]);
#pragma unroll
                for (int r = 0; r < 8; r++) acc[r] = ffma2(av[r].z, w2, acc[r]);
#pragma unroll
                for (int r = 0; r < 8; r++) acc[r] = ffma2(av[r].w, w3, acc[r]);
            }
        }
        const float2 bv = *reinterpret_cast<const float2*>(&nb[2 * lane]);
#pragma unroll
        for (int r = 0; r < 8; r++) {
            int row = m0 + r0 + r;
            if (row >= NN) break;  // warp-uniform
            float2 o = make_float2(acc[r].x + bv.x, acc[r].y + bv.y);
            *reinterpret_cast<float2*>(&hout[(size_t)row * 64 + 2 * lane]) = o;
        }
    }
}

// ---------------- CSR scan (single block) -------------------------------------
__global__ void scan_kernel(const int* __restrict__ deg, int* __restrict__ rowptr,
                            int* __restrict__ cursor) {
    __shared__ int sh[1024];
    const int tid = threadIdx.x;
    const int CH = (NN + 1023) / 1024;
    const int base = tid * CH;
    int s = 0;
    for (int i = 0; i < CH; i++) {
        int j = base + i;
        if (j < NN) s += deg[j];
    }
    sh[tid] = s;
    __syncthreads();
    for (int off = 1; off < 1024; off <<= 1) {
        int v = (tid >= off) ? sh[tid - off] : 0;
        __syncthreads();
        sh[tid] += v;
        __syncthreads();
    }
    int run = (tid > 0) ? sh[tid - 1] : 0;
    for (int i = 0; i < CH; i++) {
        int j = base + i;
        if (j < NN) {
            rowptr[j] = run;
            cursor[j] = run;
            run += deg[j];
        }
    }
    if (tid == 0) rowptr[NN] = sh[1023];
}

// thread-per-edge scatter: CSR slot -> packed {src, original edge id}
__global__ void scatter_perm_kernel(const int* __restrict__ src,
                                    const int* __restrict__ dst,
                                    int* __restrict__ cursor,
                                    int2* __restrict__ pp) {
    int e = blockIdx.x * blockDim.x + threadIdx.x;
    if (e < EE) {
        int idx = atomicAdd(&cursor[dst[e]], 1);
        pp[idx] = make_int2(src[e], e);
    }
}

// ---------------- softmax aggregation (R14 shape + L2 prefetch) ---------------
// One warp per destination node; lane owns features {2l,2l+1}. Depth-2 data
// pipeline (measured-best issue%). Register-free prefetch.global.L2 pulls the
// ea2 line for edge j+8 toward L2, converting demand DRAM misses (~577cyc)
// into L2 hits (~240cyc) without data registers or scoreboard pressure.
__global__ __launch_bounds__(256, 6) void agg_kernel(const float* __restrict__ z,
                                                     const __half2* __restrict__ ea2,
                                                     const int2* __restrict__ pp,
                                                     const int* __restrict__ rowptr,
                                                     const float* __restrict__ t_ptr,
                                                     float* __restrict__ out) {
    const int w = (blockIdx.x * blockDim.x + threadIdx.x) >> 5;
    if (w >= NN) return;
    const int lane = threadIdx.x & 31;
    const float t2 = *t_ptr * 1.4426950408889634f;  // t * log2(e)

    const int beg = rowptr[w], end = rowptr[w + 1];
    float2 accP = make_float2(0.f, 0.f);
    float2 accM = make_float2(0.f, 0.f);

    const __half2* ea_l = ea2 + lane;
    const float2* z_l = reinterpret_cast<const float2*>(z) + lane;

    __half2 e0 = __float2half2_rn(0.f), e1 = e0;
    float2 z0 = make_float2(0.f, 0.f), z1 = z0;
    int2 pp2 = make_int2(0, 0);
    {
        if (beg < end) {
            int2 p = pp[beg];
            e0 = __ldcs(ea_l + (size_t)p.y * 32);
            z0 = z_l[(size_t)p.x * 32];
        }
        if (beg + 1 < end) {
            int2 p = pp[beg + 1];
            e1 = __ldcs(ea_l + (size_t)p.y * 32);
            z1 = z_l[(size_t)p.x * 32];
        }
        if (beg + 2 < end) pp2 = pp[beg + 2];
        // warm the prefetch window for the first iterations
#pragma unroll
        for (int q = 3; q < 8; q++) {
            if (beg + q < end) {
                int pe = __ldg(&pp[beg + q].y);
                asm volatile("prefetch.global.L2 [%0];"
                             :: "l"(ea_l + (size_t)pe * 32) : "memory");
            }
        }
    }

    for (int j = beg; j < end; j++) {
        // issue stage j+2 loads; fetch pp for j+3
        __half2 e2 = __float2half2_rn(0.f);
        float2 z2 = make_float2(0.f, 0.f);
        int2 pp3 = make_int2(0, 0);
        if (j + 2 < end) {
            e2 = __ldcs(ea_l + (size_t)pp2.y * 32);
            z2 = z_l[(size_t)pp2.x * 32];
        }
        if (j + 3 < end) pp3 = pp[j + 3];
        // register-free L2 prefetch of ea2 line for edge j+8
        if (j + 8 < end) {
            int pe = __ldg(&pp[j + 8].y);
            asm volatile("prefetch.global.L2 [%0];"
                         :: "l"(ea_l + (size_t)pe * 32) : "memory");
        }

        float2 ev = __half22float2(e0);
        float m0 = fmaxf(z0.x + ev.x, 0.f) + EPS_MSG;
        float m1 = fmaxf(z0.y + ev.y, 0.f) + EPS_MSG;
        // softmax without max-shift: exp args bounded (msg small, t = O(1))
        float p0 = exp2f(m0 * t2);
        float p1 = exp2f(m1 * t2);
        accP.x += p0;
        accP.y += p1;
        accM.x = fmaf(m0, p0, accM.x);
        accM.y = fmaf(m1, p1, accM.y);

        e0 = e1; z0 = z1;
        e1 = e2; z1 = z2;
        pp2 = pp3;
    }
    const float2 zd = z_l[(size_t)w * 32];
    float2 o;
    o.x = (end > beg ? __fdividef(accM.x, accP.x) : 0.f) + zd.x;
    o.y = (end > beg ? __fdividef(accM.y, accP.y) : 0.f) + zd.y;
    *(reinterpret_cast<float2*>(out) + (size_t)w * 32 + lane) = o;
}

// ---------------- GEMM NOUT=64, K=128, K-chunked smem (32 KB) -----------------
__global__ __launch_bounds__(256, 6) void gemm64_kernel(const float* __restrict__ A,
                                                        const float* __restrict__ W,
                                                        const float* __restrict__ bias,
                                                        const float* __restrict__ resid,
                                                        float* __restrict__ hout,
                                                        const float* __restrict__ png,
                                                        const float* __restrict__ pnb,
                                                        float* __restrict__ zout, int M) {
    constexpr int K = 128, KC = 64;
    __shared__ float sA[64 * KC];  // 16 KB
    __shared__ float sW[KC * 64];  // 16 KB
    const int tid = threadIdx.x;
    const int m0 = blockIdx.x * 64;
    const int warp = tid >> 5, lane = tid & 31;
    const int r0 = warp * 8;

    float2 acc[8];
#pragma unroll
    for (int r = 0; r < 8; r++) acc[r] = make_float2(0.f, 0.f);

#pragma unroll
    for (int kc = 0; kc < K; kc += KC) {
        if (kc) __syncthreads();
        for (int idx = tid * 4; idx < 64 * KC; idx += 1024) {
            int row = idx / KC, col = idx % KC;
            float4 v = make_float4(0.f, 0.f, 0.f, 0.f);
            if (m0 + row < M)
                v = *reinterpret_cast<const float4*>(&A[(size_t)(m0 + row) * K + kc + col]);
            *reinterpret_cast<float4*>(&sA[idx]) = v;
        }
        for (int idx = tid * 4; idx < KC * 64; idx += 1024) {
            int row = idx / 64, col = idx % 64;
            *reinterpret_cast<float4*>(&sW[idx]) =
                *reinterpret_cast<const float4*>(&W[(kc + row) * 64 + col]);
        }
        __syncthreads();

#pragma unroll 4
        for (int k4 = 0; k4 < KC; k4 += 4) {
            float4 av[8];
#pragma unroll
            for (int r = 0; r < 8; r++)
                av[r] = *reinterpret_cast<const float4*>(&sA[(r0 + r) * KC + k4]);
            float2 w0 = *reinterpret_cast<const float2*>(&sW[(k4 + 0) * 64 + 2 * lane]);
            float2 w1 = *reinterpret_cast<const float2*>(&sW[(k4 + 1) * 64 + 2 * lane]);
            float2 w2 = *reinterpret_cast<const float2*>(&sW[(k4 + 2) * 64 + 2 * lane]);
            float2 w3 = *reinterpret_cast<const float2*>(&sW[(k4 + 3) * 64 + 2 * lane]);
#pragma unroll
            for (int r = 0; r < 8; r++) acc[r] = ffma2(av[r].x, w0, acc[r]);
#pragma unroll
            for (int r = 0; r < 8; r++) acc[r] = ffma2(av[r].y, w1, acc[r]);
#pragma unroll
            for (int r = 0; r < 8; r++) acc[r] = ffma2(av[r].z, w2, acc[r]);
#pragma unroll
            for (int r = 0; r < 8; r++) acc[r] = ffma2(av[r].w, w3, acc[r]);
        }
    }

    const float2 bv = *reinterpret_cast<const float2*>(&bias[2 * lane]);
    float2 gv = make_float2(1.f, 1.f), tv = make_float2(0.f, 0.f);
    if (zout) {
        gv = *reinterpret_cast<const float2*>(&png[2 * lane]);
        tv = *reinterpret_cast<const float2*>(&pnb[2 * lane]);
    }
#pragma unroll
    for (int r = 0; r < 8; r++) {
        int row = m0 + r0 + r;
        if (row >= M) break;  // warp-uniform
        float2 o = make_float2(acc[r].x + bv.x, acc[r].y + bv.y);
        if (resid) {
            float2 rv = *reinterpret_cast<const float2*>(&resid[(size_t)row * 64 + 2 * lane]);
            o.x += rv.x;
            o.y += rv.y;
        }
        *reinterpret_cast<float2*>(&hout[(size_t)row * 64 + 2 * lane]) = o;
        if (zout) {
            float s1 = o.x + o.y;
            float s2 = o.x * o.x + o.y * o.y;
#pragma unroll
            for (int off = 16; off; off >>= 1) {
                s1 += __shfl_xor_sync(0xffffffffu, s1, off);
                s2 += __shfl_xor_sync(0xffffffffu, s2, off);
            }
            float mean = s1 * (1.f / 64.f);
            float var = s2 * (1.f / 64.f) - mean * mean;
            float rstd = rsqrtf(var + LN_EPS);
            float z0 = fmaxf((o.x - mean) * rstd * gv.x + tv.x, 0.f);
            float z1 = fmaxf((o.y - mean) * rstd * gv.y + tv.y, 0.f);
            *reinterpret_cast<float2*>(&zout[(size_t)row * 64 + 2 * lane]) =
                make_float2(z0, z1);
        }
    }
}

// ---------------- GEMM NOUT=128, K=64, K-chunked smem (24 KB), fused LN+ReLU --
__global__ __launch_bounds__(256, 4) void gemm128_kernel(const float* __restrict__ A,
                                                         const float* __restrict__ W,
                                                         const float* __restrict__ bias,
                                                         const float* __restrict__ lng,
                                                         const float* __restrict__ lnb,
                                                         float* __restrict__ C, int M) {
    constexpr int K = 64, KC = 32;
    __shared__ float sA[64 * KC];   // 8 KB
    __shared__ float sW[KC * 128];  // 16 KB
    const int tid = threadIdx.x;
    const int m0 = blockIdx.x * 64;
    const int warp = tid >> 5, lane = tid & 31;
    const int r0 = warp * 8;

    float2 acc[8][2];
#pragma unroll
    for (int r = 0; r < 8; r++) {
        acc[r][0] = make_float2(0.f, 0.f);
        acc[r][1] = make_float2(0.f, 0.f);
    }

#pragma unroll
    for (int kc = 0; kc < K; kc += KC) {
        if (kc) __syncthreads();
        for (int idx = tid * 4; idx < 64 * KC; idx += 1024) {
            int row = idx / KC, col = idx % KC;
            float4 v = make_float4(0.f, 0.f, 0.f, 0.f);
            if (m0 + row < M)
                v = *reinterpret_cast<const float4*>(&A[(size_t)(m0 + row) * K + kc + col]);
            *reinterpret_cast<float4*>(&sA[idx]) = v;
        }
        for (int idx = tid * 4; idx < KC * 128; idx += 1024) {
            int row = idx / 128, col = idx % 128;
            *reinterpret_cast<float4*>(&sW[idx]) =
                *reinterpret_cast<const float4*>(&W[(kc + row) * 128 + col]);
        }
        __syncthreads();

#pragma unroll 2
        for (int k4 = 0; k4 < KC; k4 += 4) {
            float4 av[8];
#pragma unroll
            for (int r = 0; r < 8; r++)
                av[r] = *reinterpret_cast<const float4*>(&sA[(r0 + r) * KC + k4]);
            float4 wa = *reinterpret_cast<const float4*>(&sW[(k4 + 0) * 128 + 4 * lane]);
            float4 wb = *reinterpret_cast<const float4*>(&sW[(k4 + 1) * 128 + 4 * lane]);
            float4 wc = *reinterpret_cast<const float4*>(&sW[(k4 + 2) * 128 + 4 * lane]);
            float4 wd = *reinterpret_cast<const float4*>(&sW[(k4 + 3) * 128 + 4 * lane]);
#pragma unroll
            for (int r = 0; r < 8; r++) {
                acc[r][0] = ffma2(av[r].x, make_float2(wa.x, wa.y), acc[r][0]);
                acc[r][1] = ffma2(av[r].x, make_float2(wa.z, wa.w), acc[r][1]);
            }
#pragma unroll
            for (int r = 0; r < 8; r++) {
                acc[r][0] = ffma2(av[r].y, make_float2(wb.x, wb.y), acc[r][0]);
                acc[r][1] = ffma2(av[r].y, make_float2(wb.z, wb.w), acc[r][1]);
            }
#pragma unroll
            for (int r = 0; r < 8; r++) {
                acc[r][0] = ffma2(av[r].z, make_float2(wc.x, wc.y), acc[r][0]);
                acc[r][1] = ffma2(av[r].z, make_float2(wc.z, wc.w), acc[r][1]);
            }
#pragma unroll
            for (int r = 0; r < 8; r++) {
                acc[r][0] = ffma2(av[r].w, make_float2(wd.x, wd.y), acc[r][0]);
                acc[r][1] = ffma2(av[r].w, make_float2(wd.z, wd.w), acc[r][1]);
            }
        }
    }

    const float4 bv = *reinterpret_cast<const float4*>(&bias[4 * lane]);
    const float4 gv = *reinterpret_cast<const float4*>(&lng[4 * lane]);
    const float4 tv = *reinterpret_cast<const float4*>(&lnb[4 * lane]);
#pragma unroll
    for (int r = 0; r < 8; r++) {
        int row = m0 + r0 + r;
        if (row >= M) break;  // warp-uniform
        float v0 = acc[r][0].x + bv.x, v1 = acc[r][0].y + bv.y;
        float v2 = acc[r][1].x + bv.z, v3 = acc[r][1].y + bv.w;
        float s1 = v0 + v1 + v2 + v3;
        float s2 = v0 * v0 + v1 * v1 + v2 * v2 + v3 * v3;
#pragma unroll
        for (int off = 16; off; off >>= 1) {
            s1 += __shfl_xor_sync(0xffffffffu, s1, off);
            s2 += __shfl_xor_sync(0xffffffffu, s2, off);
        }
        float mean = s1 * (1.f / 128.f);
        float var = s2 * (1.f / 128.f) - mean * mean;
        float rstd = rsqrtf(var + LN_EPS);
        v0 = fmaxf((v0 - mean) * rstd * gv.x + tv.x, 0.f);
        v1 = fmaxf((v1 - mean) * rstd * gv.y + tv.y, 0.f);
        v2 = fmaxf((v2 - mean) * rstd * gv.z + tv.z, 0.f);
        v3 = fmaxf((v3 - mean) * rstd * gv.w + tv.w, 0.f);
        *reinterpret_cast<float4*>(&C[(size_t)row * 128 + 4 * lane]) =
            make_float4(v0, v1, v2, v3);
    }
}

// ---------------- launch ------------------------------------------------------
extern "C" void kernel_launch(void* const* d_in, const int* in_sizes, int n_in,
                              void* d_out, int out_size) {
    const float* x      = (const float*)d_in[0];
    const int*   ei     = (const int*)d_in[1];
    const float* eattr  = (const float*)d_in[2];
    const float* node_W = (const float*)d_in[3];
    const float* node_b = (const float*)d_in[4];
    const float* edge_W = (const float*)d_in[5];
    const float* edge_b = (const float*)d_in[6];
    const float* t      = (const float*)d_in[7];
    const float* mlp1_W = (const float*)d_in[8];
    const float* mlp1_b = (const float*)d_in[9];
    const float* ln_g   = (const float*)d_in[10];
    const float* ln_b   = (const float*)d_in[11];
    const float* mlp2_W = (const float*)d_in[12];
    const float* mlp2_b = (const float*)d_in[13];
    const float* blk_g  = (const float*)d_in[14];
    const float* blk_b  = (const float*)d_in[15];
    float* out = (float*)d_out;

    const int* src = ei;
    const int* dst = ei + EE;

    __half2* p_ea2;
    float *p_h, *p_z, *p_agg, *p_t1;
    int *p_deg, *p_rowptr, *p_cursor;
    int2* p_pp;
    cudaGetSymbolAddress((void**)&p_ea2, g_ea2);
    cudaGetSymbolAddress((void**)&p_h, g_h);
    cudaGetSymbolAddress((void**)&p_z, g_z);
    cudaGetSymbolAddress((void**)&p_agg, g_agg);
    cudaGetSymbolAddress((void**)&p_t1, g_t1);
    cudaGetSymbolAddress((void**)&p_deg, g_deg);
    cudaGetSymbolAddress((void**)&p_rowptr, g_rowptr);
    cudaGetSymbolAddress((void**)&p_cursor, g_cursor);
    cudaGetSymbolAddress((void**)&p_pp, g_pp);

    const int warpBlocks = (NN * 32 + 255) / 256;  // 6250 (one warp per node)
    const int gemmBlocks = (NN + 63) / 64;         // 782

    // 1) mega: edge encode (orig order) + histogram + node encoder
    cudaMemsetAsync(p_deg, 0, NN * sizeof(int));
    enc_node_kernel<<<ENCB + NODEB, 256>>>(eattr, dst, edge_W, edge_b, p_ea2,
                                           p_deg, x, node_W, node_b, p_h);
    // 2) scan, 3) scatter (packed pp)
    scan_kernel<<<1, 1024>>>(p_deg, p_rowptr, p_cursor);
    scatter_perm_kernel<<<(EE + 255) / 256, 256>>>(src, dst, p_cursor, p_pp);

    // 4..) layers — agg layer 0 lands in the ncu capture slot
    for (int i = 0; i < LL; i++) {
        const float* zin = (i == 0) ? p_h : p_z;
        agg_kernel<<<warpBlocks, 256>>>(zin, p_ea2, p_pp, p_rowptr, t + i, p_agg);
        gemm128_kernel<<<gemmBlocks, 256>>>(
            p_agg, mlp1_W + (size_t)i * 64 * 128, mlp1_b + i * 128,
            ln_g + i * 128, ln_b + i * 128, p_t1, NN);
        const bool last = (i == LL - 1);
        const float* png = last ? blk_g : blk_g + (i + 1) * HH;  // final norm uses blk[0]
        const float* pnb = last ? blk_b : blk_b + (i + 1) * HH;
        float* zo = last ? out : p_z;
        gemm64_kernel<<<gemmBlocks, 256>>>(
            p_t1, mlp2_W + (size_t)i * 128 * 64, mlp2_b + i * 64,
            (i > 0 ? p_h : nullptr), p_h, png, pnb, zo, NN);
    }
}